// round 15
// baseline (speedup 1.0000x reference)
#include <cuda_runtime.h>
#include <cuda_fp16.h>
#include <cstdint>

#define M_DIM 4096
#define K_DIM 4096
#define B_DIM 4
#define N_DIM 2048
#define BN_DIM (B_DIM * N_DIM)      // 8192

// GEMM tiling: CTA 128x128, 4 warps of 64x64, BK=64 (at the legacy-HMMA
// MAC-rate wall: ~157.5 dense MAC/cyc/SMSP)
#define BM 128
#define BN 128
#define BK 64
#define NSTAGE 3
#define PADK 72                      // pitch in halves (144 B): conflict-free ldmatrix
#define TRB (PADK * 2)               // tile row bytes = 144
#define A_TILE_BYTES (BM * TRB)      // 18432
#define B_TILE_BYTES (BN * TRB)      // 18432
#define STAGE_BYTES (A_TILE_BYTES + B_TILE_BYTES)   // 36864
#define SMEM_TOTAL (NSTAGE * STAGE_BYTES)           // 110592 -> 2 CTAs/SM
#define NKT (K_DIM / BK)             // 64

// ---------------- scratch ----------------------------------------------------
__device__ __align__(1024) __half g_Wh[(size_t)M_DIM * K_DIM];
__device__ __align__(1024) __half g_Xh[(size_t)BN_DIM * K_DIM];

// ---------------- helpers ----------------------------------------------------
__device__ __forceinline__ uint32_t smem_u32(const void* p) {
    uint32_t a;
    asm("{ .reg .u64 t; cvta.to.shared.u64 t, %1; cvt.u32.u64 %0, t; }" : "=r"(a) : "l"(p));
    return a;
}

#define CP16(dst_u32, src_ptr) \
    asm volatile("cp.async.cg.shared.global [%0], [%1], 16;" \
                 :: "r"(dst_u32), "l"(src_ptr) : "memory")
#define CP_COMMIT() asm volatile("cp.async.commit_group;" ::: "memory")
#define CP_WAIT(n)  asm volatile("cp.async.wait_group %0;" :: "n"(n) : "memory")

__device__ __forceinline__ void ldsm_x4(uint32_t* r, uint32_t addr) {
    asm volatile("ldmatrix.sync.aligned.m8n8.x4.shared.b16 {%0,%1,%2,%3}, [%4];"
        : "=r"(r[0]), "=r"(r[1]), "=r"(r[2]), "=r"(r[3]) : "r"(addr));
}

__device__ __forceinline__ void mma16816(float* d, const uint32_t* a, const uint32_t* b) {
    asm volatile(
        "mma.sync.aligned.m16n8k16.row.col.f32.f16.f16.f32 "
        "{%0,%1,%2,%3}, {%4,%5,%6,%7}, {%8,%9}, {%0,%1,%2,%3};"
        : "+f"(d[0]), "+f"(d[1]), "+f"(d[2]), "+f"(d[3])
        : "r"(a[0]), "r"(a[1]), "r"(a[2]), "r"(a[3]), "r"(b[0]), "r"(b[1]));
}

// ---------------- prep kernels -----------------------------------------------
// Fused zero + deterministic CSR scatter: build each dense fp16 W row in smem,
// write once coalesced.  Duplicate columns folded in fp32 (sorted runs).
__global__ void __launch_bounds__(256) buildw_kernel(
    const float* __restrict__ values, const int* __restrict__ row_offsets,
    const int* __restrict__ cols) {
    __shared__ __half row[K_DIM];                    // 8 KB
    const int m = blockIdx.x;

    uint4* r4 = reinterpret_cast<uint4*>(row);
    #pragma unroll
    for (int i = threadIdx.x; i < K_DIM / 8; i += 256)
        r4[i] = make_uint4(0u, 0u, 0u, 0u);
    __syncthreads();

    const int s = row_offsets[m], e = row_offsets[m + 1];
    for (int j = s + threadIdx.x; j < e; j += 256) {
        const int c = cols[j];
        if (j > s && cols[j - 1] == c) continue;     // not head of duplicate run
        float sum = values[j];
        int jj = j + 1;
        while (jj < e && cols[jj] == c) { sum += values[jj]; jj++; }
        row[c] = __float2half_rn(sum);
    }
    __syncthreads();

    uint4* dst = reinterpret_cast<uint4*>(g_Wh + (size_t)m * K_DIM);
    #pragma unroll
    for (int i = threadIdx.x; i < K_DIM / 8; i += 256)
        dst[i] = r4[i];
}

// fp32 -> fp16 conversion of a range of X, 8 elems/thread, single 16B store.
__global__ void __launch_bounds__(256) convx_kernel(const float* __restrict__ x,
                                                    size_t base) {
    const size_t i = base + ((size_t)blockIdx.x * 256 + threadIdx.x) * 8;
    const float4 a = *reinterpret_cast<const float4*>(&x[i]);
    const float4 b = *reinterpret_cast<const float4*>(&x[i + 4]);
    __half2 h[4];
    h[0] = __halves2half2(__float2half_rn(a.x), __float2half_rn(a.y));
    h[1] = __halves2half2(__float2half_rn(a.z), __float2half_rn(a.w));
    h[2] = __halves2half2(__float2half_rn(b.x), __float2half_rn(b.y));
    h[3] = __halves2half2(__float2half_rn(b.z), __float2half_rn(b.w));
    *reinterpret_cast<uint4*>(&g_Xh[i]) = *reinterpret_cast<const uint4*>(h);
}

// ---------------- GEMM -------------------------------------------------------
// C[M, bn_base:bn_base+32*BN] = Wh * Xh^T slice, fp32 accumulate.
// 128 threads, warp grid 2x2, warp tile 64x64.  2 CTAs/SM.
__global__ void __launch_bounds__(128, 2) gemm_kernel(float* __restrict__ out,
                                                      int bn_base) {
    extern __shared__ char smem[];
    const int tid  = threadIdx.x;
    const int wid  = tid >> 5;
    const int lane = tid & 31;
    const int grp  = lane >> 2;
    const int tig  = lane & 3;
    const int wm0  = (wid & 1) * 64;
    const int wn0  = (wid >> 1) * 64;
    const int m0   = blockIdx.x * BM;
    const int bn0  = bn_base + blockIdx.y * BN;

    const uint32_t sbase = smem_u32(smem);

    // ldmatrix lane-derived address components
    const int a_row_l = (lane & 7) + 8 * ((lane >> 3) & 1);
    const int a_kx    = 16 * ((lane >> 4) & 1);
    const int b_row_l = (lane & 7) + 8 * ((lane >> 4) & 1);
    const int b_kx    = 16 * ((lane >> 3) & 1);

    const __half* gA = g_Wh + (size_t)m0  * K_DIM;
    const __half* gB = g_Xh + (size_t)bn0 * K_DIM;

    // cp.async per stage: 1024 chunks A + 1024 chunks B (16 B each), 128 thr
    // -> 8 A + 8 B chunks per thread.  chunk c: row = c>>3, ch = c&7.
    #define LOAD_STAGE(stg, ktidx) do {                                         \
        const uint32_t sb_ = sbase + (stg) * STAGE_BYTES;                       \
        const int kh_ = (ktidx) * BK;                                           \
        _Pragma("unroll")                                                       \
        for (int i_ = 0; i_ < 8; i_++) {                                        \
            const int c_   = tid + i_ * 128;                                    \
            const int row_ = c_ >> 3, ch_ = c_ & 7;                             \
            const uint32_t d_ = sb_ + row_ * TRB + ch_ * 16;                    \
            const size_t  g_  = (size_t)row_ * K_DIM + kh_ + ch_ * 8;           \
            CP16(d_, gA + g_);                                                  \
            CP16(d_ + A_TILE_BYTES, gB + g_);                                   \
        }                                                                       \
    } while (0)

    #pragma unroll
    for (int s = 0; s < NSTAGE - 1; s++) { LOAD_STAGE(s, s); CP_COMMIT(); }

    float acc[4][8][4];
    #pragma unroll
    for (int mt = 0; mt < 4; mt++)
        #pragma unroll
        for (int nt = 0; nt < 8; nt++)
            #pragma unroll
            for (int r = 0; r < 4; r++) acc[mt][nt][r] = 0.f;

    for (int kt = 0; kt < NKT; kt++) {
        CP_WAIT(NSTAGE - 2);
        __syncthreads();
        if (kt + NSTAGE - 1 < NKT) LOAD_STAGE((kt + NSTAGE - 1) % NSTAGE, kt + NSTAGE - 1);
        CP_COMMIT();

        const uint32_t st = sbase + (kt % NSTAGE) * STAGE_BYTES;
        const uint32_t sA = st;
        const uint32_t sB = st + A_TILE_BYTES;

        #pragma unroll
        for (int ks = 0; ks < 4; ks++) {
            const int kb = ks * 32;
            uint32_t bf[8][2];
            #pragma unroll
            for (int ntp = 0; ntp < 4; ntp++) {
                uint32_t r[4];
                ldsm_x4(r, sB + (wn0 + 16 * ntp + b_row_l) * TRB + kb + b_kx);
                bf[2 * ntp][0]     = r[0];
                bf[2 * ntp][1]     = r[1];
                bf[2 * ntp + 1][0] = r[2];
                bf[2 * ntp + 1][1] = r[3];
            }
            uint32_t ah[4][4];
            #pragma unroll
            for (int mt = 0; mt < 4; mt++)
                ldsm_x4(ah[mt], sA + (wm0 + 16 * mt + a_row_l) * TRB + kb + a_kx);
            #pragma unroll
            for (int mt = 0; mt < 4; mt++)
                #pragma unroll
                for (int nt = 0; nt < 8; nt++)
                    mma16816(acc[mt][nt], ah[mt], bf[nt]);
        }
    }

    // epilogue
    const int b  = bn0 >> 11;               // / N_DIM
    const int nb = bn0 & (N_DIM - 1);
    float* ob = out + (size_t)b * M_DIM * N_DIM;
    #pragma unroll
    for (int mt = 0; mt < 4; mt++) {
        const int row = m0 + wm0 + 16 * mt + grp;
        #pragma unroll
        for (int nt = 0; nt < 8; nt++) {
            const int col = nb + wn0 + 8 * nt + 2 * tig;
            *reinterpret_cast<float2*>(ob + (size_t)row * N_DIM + col) =
                make_float2(acc[mt][nt][0], acc[mt][nt][1]);
            *reinterpret_cast<float2*>(ob + (size_t)(row + 8) * N_DIM + col) =
                make_float2(acc[mt][nt][2], acc[mt][nt][3]);
        }
    }
}

// ---------------- host side --------------------------------------------------
extern "C" void kernel_launch(void* const* d_in, const int* in_sizes, int n_in,
                              void* d_out, int out_size) {
    const float* x           = (const float*)d_in[0];  // [B, N, K] == [BN, K]
    const float* values      = (const float*)d_in[1];
    const int*   row_offsets = (const int*)  d_in[2];
    const int*   col_indices = (const int*)  d_in[3];
    float*       out         = (float*)d_out;
    (void)in_sizes; (void)n_in; (void)out_size;

    static bool inited = false;
    static cudaStream_t sW, sG;
    static cudaEvent_t evFork, evW, evX0, evG0;
    if (!inited) {
        cudaStreamCreateWithFlags(&sW, cudaStreamNonBlocking);
        cudaStreamCreateWithFlags(&sG, cudaStreamNonBlocking);
        cudaEventCreateWithFlags(&evFork, cudaEventDisableTiming);
        cudaEventCreateWithFlags(&evW,    cudaEventDisableTiming);
        cudaEventCreateWithFlags(&evX0,   cudaEventDisableTiming);
        cudaEventCreateWithFlags(&evG0,   cudaEventDisableTiming);
        cudaFuncSetAttribute(gemm_kernel,
                             cudaFuncAttributeMaxDynamicSharedMemorySize, SMEM_TOTAL);
        inited = true;
    }

    const size_t xN   = (size_t)BN_DIM * K_DIM;   // 33.5M halves
    const size_t half = xN / 2;
    const unsigned cblk = (unsigned)(half / 8 / 256);

    // fork sW from the (captured) main stream
    cudaEventRecord(evFork, 0);
    cudaStreamWaitEvent(sW, evFork, 0);

    // W build on sW, X conversion chunks on the main stream
    buildw_kernel<<<M_DIM, 256, 0, sW>>>(values, row_offsets, col_indices);
    cudaEventRecord(evW, sW);

    convx_kernel<<<cblk, 256>>>(x, 0);
    cudaEventRecord(evX0, 0);
    convx_kernel<<<cblk, 256>>>(x, half);

    // gemm half 0 on sG: needs W + X[0:half)
    cudaStreamWaitEvent(sG, evW, 0);
    cudaStreamWaitEvent(sG, evX0, 0);
    gemm_kernel<<<dim3(M_DIM / BM, BN_DIM / BN / 2), 128, SMEM_TOTAL, sG>>>(out, 0);
    cudaEventRecord(evG0, sG);

    // gemm half 1 on main stream: needs W + X[half:) (implicit on this stream)
    cudaStreamWaitEvent(0, evW, 0);
    gemm_kernel<<<dim3(M_DIM / BM, BN_DIM / BN / 2), 128, SMEM_TOTAL>>>(out, BN_DIM / 2);

    // join
    cudaStreamWaitEvent(0, evG0, 0);
}

// round 16
// speedup vs baseline: 1.0026x; 1.0026x over previous
#include <cuda_runtime.h>
#include <cuda_fp16.h>
#include <cstdint>

#define M_DIM 4096
#define K_DIM 4096
#define B_DIM 4
#define N_DIM 2048
#define BN_DIM (B_DIM * N_DIM)      // 8192

// GEMM tiling: CTA 128x128, 4 warps of 64x64, BK=64 (at the legacy-HMMA
// MAC-rate wall: ~157.5 dense MAC/cyc/SMSP)
#define BM 128
#define BN 128
#define BK 64
#define NSTAGE 3
#define PADK 72                      // pitch in halves (144 B): conflict-free ldmatrix
#define TRB (PADK * 2)               // tile row bytes = 144
#define A_TILE_BYTES (BM * TRB)      // 18432
#define B_TILE_BYTES (BN * TRB)      // 18432
#define STAGE_BYTES (A_TILE_BYTES + B_TILE_BYTES)   // 36864
#define SMEM_TOTAL (NSTAGE * STAGE_BYTES)           // 110592 -> 2 CTAs/SM
#define NKT (K_DIM / BK)             // 64

// ---------------- scratch ----------------------------------------------------
__device__ __align__(1024) __half g_Wh[(size_t)M_DIM * K_DIM];
__device__ __align__(1024) __half g_Xh[(size_t)BN_DIM * K_DIM];

// ---------------- helpers ----------------------------------------------------
__device__ __forceinline__ uint32_t smem_u32(const void* p) {
    uint32_t a;
    asm("{ .reg .u64 t; cvta.to.shared.u64 t, %1; cvt.u32.u64 %0, t; }" : "=r"(a) : "l"(p));
    return a;
}

#define CP16(dst_u32, src_ptr) \
    asm volatile("cp.async.cg.shared.global [%0], [%1], 16;" \
                 :: "r"(dst_u32), "l"(src_ptr) : "memory")
#define CP_COMMIT() asm volatile("cp.async.commit_group;" ::: "memory")
#define CP_WAIT(n)  asm volatile("cp.async.wait_group %0;" :: "n"(n) : "memory")

__device__ __forceinline__ void ldsm_x4(uint32_t* r, uint32_t addr) {
    asm volatile("ldmatrix.sync.aligned.m8n8.x4.shared.b16 {%0,%1,%2,%3}, [%4];"
        : "=r"(r[0]), "=r"(r[1]), "=r"(r[2]), "=r"(r[3]) : "r"(addr));
}

__device__ __forceinline__ void mma16816(float* d, const uint32_t* a, const uint32_t* b) {
    asm volatile(
        "mma.sync.aligned.m16n8k16.row.col.f32.f16.f16.f32 "
        "{%0,%1,%2,%3}, {%4,%5,%6,%7}, {%8,%9}, {%0,%1,%2,%3};"
        : "+f"(d[0]), "+f"(d[1]), "+f"(d[2]), "+f"(d[3])
        : "r"(a[0]), "r"(a[1]), "r"(a[2]), "r"(a[3]), "r"(b[0]), "r"(b[1]));
}

// ---------------- prep kernels -----------------------------------------------
// Fused zero + deterministic CSR scatter: build each dense fp16 W row in smem,
// write once coalesced.  Duplicate columns folded in fp32 (sorted runs).
__global__ void __launch_bounds__(256) buildw_kernel(
    const float* __restrict__ values, const int* __restrict__ row_offsets,
    const int* __restrict__ cols) {
    __shared__ __half row[K_DIM];                    // 8 KB
    const int m = blockIdx.x;

    uint4* r4 = reinterpret_cast<uint4*>(row);
    #pragma unroll
    for (int i = threadIdx.x; i < K_DIM / 8; i += 256)
        r4[i] = make_uint4(0u, 0u, 0u, 0u);
    __syncthreads();

    const int s = row_offsets[m], e = row_offsets[m + 1];
    for (int j = s + threadIdx.x; j < e; j += 256) {
        const int c = cols[j];
        if (j > s && cols[j - 1] == c) continue;     // not head of duplicate run
        float sum = values[j];
        int jj = j + 1;
        while (jj < e && cols[jj] == c) { sum += values[jj]; jj++; }
        row[c] = __float2half_rn(sum);
    }
    __syncthreads();

    uint4* dst = reinterpret_cast<uint4*>(g_Wh + (size_t)m * K_DIM);
    #pragma unroll
    for (int i = threadIdx.x; i < K_DIM / 8; i += 256)
        dst[i] = r4[i];
}

// fp32 -> fp16 conversion of a range of X, 8 elems/thread, single 16B store.
__global__ void __launch_bounds__(256) convx_kernel(const float* __restrict__ x,
                                                    size_t base) {
    const size_t i = base + ((size_t)blockIdx.x * 256 + threadIdx.x) * 8;
    const float4 a = *reinterpret_cast<const float4*>(&x[i]);
    const float4 b = *reinterpret_cast<const float4*>(&x[i + 4]);
    __half2 h[4];
    h[0] = __halves2half2(__float2half_rn(a.x), __float2half_rn(a.y));
    h[1] = __halves2half2(__float2half_rn(a.z), __float2half_rn(a.w));
    h[2] = __halves2half2(__float2half_rn(b.x), __float2half_rn(b.y));
    h[3] = __halves2half2(__float2half_rn(b.z), __float2half_rn(b.w));
    *reinterpret_cast<uint4*>(&g_Xh[i]) = *reinterpret_cast<const uint4*>(h);
}

// ---------------- GEMM -------------------------------------------------------
// C[M, bn_base:bn_base+nbn) = Wh * Xh^T slice, fp32 accumulate.
// 128 threads, warp grid 2x2, warp tile 64x64.  2 CTAs/SM.
__global__ void __launch_bounds__(128, 2) gemm_kernel(float* __restrict__ out,
                                                      int bn_base) {
    extern __shared__ char smem[];
    const int tid  = threadIdx.x;
    const int wid  = tid >> 5;
    const int lane = tid & 31;
    const int grp  = lane >> 2;
    const int tig  = lane & 3;
    const int wm0  = (wid & 1) * 64;
    const int wn0  = (wid >> 1) * 64;
    const int m0   = blockIdx.x * BM;
    const int bn0  = bn_base + blockIdx.y * BN;

    const uint32_t sbase = smem_u32(smem);

    // ldmatrix lane-derived address components
    const int a_row_l = (lane & 7) + 8 * ((lane >> 3) & 1);
    const int a_kx    = 16 * ((lane >> 4) & 1);
    const int b_row_l = (lane & 7) + 8 * ((lane >> 4) & 1);
    const int b_kx    = 16 * ((lane >> 3) & 1);

    const __half* gA = g_Wh + (size_t)m0  * K_DIM;
    const __half* gB = g_Xh + (size_t)bn0 * K_DIM;

    // cp.async per stage: 1024 chunks A + 1024 chunks B (16 B each), 128 thr
    // -> 8 A + 8 B chunks per thread.  chunk c: row = c>>3, ch = c&7.
    #define LOAD_STAGE(stg, ktidx) do {                                         \
        const uint32_t sb_ = sbase + (stg) * STAGE_BYTES;                       \
        const int kh_ = (ktidx) * BK;                                           \
        _Pragma("unroll")                                                       \
        for (int i_ = 0; i_ < 8; i_++) {                                        \
            const int c_   = tid + i_ * 128;                                    \
            const int row_ = c_ >> 3, ch_ = c_ & 7;                             \
            const uint32_t d_ = sb_ + row_ * TRB + ch_ * 16;                    \
            const size_t  g_  = (size_t)row_ * K_DIM + kh_ + ch_ * 8;           \
            CP16(d_, gA + g_);                                                  \
            CP16(d_ + A_TILE_BYTES, gB + g_);                                   \
        }                                                                       \
    } while (0)

    #pragma unroll
    for (int s = 0; s < NSTAGE - 1; s++) { LOAD_STAGE(s, s); CP_COMMIT(); }

    float acc[4][8][4];
    #pragma unroll
    for (int mt = 0; mt < 4; mt++)
        #pragma unroll
        for (int nt = 0; nt < 8; nt++)
            #pragma unroll
            for (int r = 0; r < 4; r++) acc[mt][nt][r] = 0.f;

    for (int kt = 0; kt < NKT; kt++) {
        CP_WAIT(NSTAGE - 2);
        __syncthreads();
        if (kt + NSTAGE - 1 < NKT) LOAD_STAGE((kt + NSTAGE - 1) % NSTAGE, kt + NSTAGE - 1);
        CP_COMMIT();

        const uint32_t st = sbase + (kt % NSTAGE) * STAGE_BYTES;
        const uint32_t sA = st;
        const uint32_t sB = st + A_TILE_BYTES;

        #pragma unroll
        for (int ks = 0; ks < 4; ks++) {
            const int kb = ks * 32;
            uint32_t bf[8][2];
            #pragma unroll
            for (int ntp = 0; ntp < 4; ntp++) {
                uint32_t r[4];
                ldsm_x4(r, sB + (wn0 + 16 * ntp + b_row_l) * TRB + kb + b_kx);
                bf[2 * ntp][0]     = r[0];
                bf[2 * ntp][1]     = r[1];
                bf[2 * ntp + 1][0] = r[2];
                bf[2 * ntp + 1][1] = r[3];
            }
            uint32_t ah[4][4];
            #pragma unroll
            for (int mt = 0; mt < 4; mt++)
                ldsm_x4(ah[mt], sA + (wm0 + 16 * mt + a_row_l) * TRB + kb + a_kx);
            #pragma unroll
            for (int mt = 0; mt < 4; mt++)
                #pragma unroll
                for (int nt = 0; nt < 8; nt++)
                    mma16816(acc[mt][nt], ah[mt], bf[nt]);
        }
    }

    // epilogue
    const int b  = bn0 >> 11;               // / N_DIM
    const int nb = bn0 & (N_DIM - 1);
    float* ob = out + (size_t)b * M_DIM * N_DIM;
    #pragma unroll
    for (int mt = 0; mt < 4; mt++) {
        const int row = m0 + wm0 + 16 * mt + grp;
        #pragma unroll
        for (int nt = 0; nt < 8; nt++) {
            const int col = nb + wn0 + 8 * nt + 2 * tig;
            *reinterpret_cast<float2*>(ob + (size_t)row * N_DIM + col) =
                make_float2(acc[mt][nt][0], acc[mt][nt][1]);
            *reinterpret_cast<float2*>(ob + (size_t)(row + 8) * N_DIM + col) =
                make_float2(acc[mt][nt][2], acc[mt][nt][3]);
        }
    }
}

// ---------------- host side --------------------------------------------------
extern "C" void kernel_launch(void* const* d_in, const int* in_sizes, int n_in,
                              void* d_out, int out_size) {
    const float* x           = (const float*)d_in[0];  // [B, N, K] == [BN, K]
    const float* values      = (const float*)d_in[1];
    const int*   row_offsets = (const int*)  d_in[2];
    const int*   col_indices = (const int*)  d_in[3];
    float*       out         = (float*)d_out;
    (void)in_sizes; (void)n_in; (void)out_size;

    static bool inited = false;
    static cudaStream_t sW, sG;
    static cudaEvent_t evFork, evW, evX0, evG0;
    if (!inited) {
        cudaStreamCreateWithFlags(&sW, cudaStreamNonBlocking);
        cudaStreamCreateWithFlags(&sG, cudaStreamNonBlocking);
        cudaEventCreateWithFlags(&evFork, cudaEventDisableTiming);
        cudaEventCreateWithFlags(&evW,    cudaEventDisableTiming);
        cudaEventCreateWithFlags(&evX0,   cudaEventDisableTiming);
        cudaEventCreateWithFlags(&evG0,   cudaEventDisableTiming);
        cudaFuncSetAttribute(gemm_kernel,
                             cudaFuncAttributeMaxDynamicSharedMemorySize, SMEM_TOTAL);
        inited = true;
    }

    const size_t xN = (size_t)BN_DIM * K_DIM;     // 33.5M halves
    const size_t xQ = xN / 4;                     // first chunk: quarter of X
    const unsigned cblkQ = (unsigned)(xQ / 8 / 256);
    const unsigned cblkR = (unsigned)((xN - xQ) / 8 / 256);

    // fork sW from the (captured) main stream
    cudaEventRecord(evFork, 0);
    cudaStreamWaitEvent(sW, evFork, 0);

    // W build on sW; X conversion (quarter, then rest) on the main stream
    buildw_kernel<<<M_DIM, 256, 0, sW>>>(values, row_offsets, col_indices);
    cudaEventRecord(evW, sW);

    convx_kernel<<<cblkQ, 256>>>(x, 0);
    cudaEventRecord(evX0, 0);
    convx_kernel<<<cblkR, 256>>>(x, xQ);

    // gemm quarter 0 on sG: needs W + X[0:xQ)
    cudaStreamWaitEvent(sG, evW, 0);
    cudaStreamWaitEvent(sG, evX0, 0);
    gemm_kernel<<<dim3(M_DIM / BM, BN_DIM / BN / 4), 128, SMEM_TOTAL, sG>>>(out, 0);
    cudaEventRecord(evG0, sG);

    // gemm rest (3/4) on main stream: needs W + X[xQ:) (implicit on this stream)
    cudaStreamWaitEvent(0, evW, 0);
    gemm_kernel<<<dim3(M_DIM / BM, 3 * (BN_DIM / BN) / 4), 128, SMEM_TOTAL>>>(
        out, BN_DIM / 4);

    // join
    cudaStreamWaitEvent(0, evG0, 0);
}

// round 17
// speedup vs baseline: 1.0053x; 1.0027x over previous
#include <cuda_runtime.h>
#include <cuda_fp16.h>
#include <cstdint>

#define M_DIM 4096
#define K_DIM 4096
#define B_DIM 4
#define N_DIM 2048
#define BN_DIM (B_DIM * N_DIM)      // 8192

// GEMM tiling: CTA 128x128, 4 warps of 64x64, BK=64 (at the legacy-HMMA
// MAC-rate wall: ~157.5 dense MAC/cyc/SMSP, rt~13 for HMMA.16816.F32)
#define BM 128
#define BN 128
#define BK 64
#define NSTAGE 3
#define PADK 72                      // pitch in halves (144 B): conflict-free ldmatrix
#define TRB (PADK * 2)               // tile row bytes = 144
#define A_TILE_BYTES (BM * TRB)      // 18432
#define B_TILE_BYTES (BN * TRB)      // 18432
#define STAGE_BYTES (A_TILE_BYTES + B_TILE_BYTES)   // 36864
#define SMEM_TOTAL (NSTAGE * STAGE_BYTES)           // 110592 -> 2 CTAs/SM
#define NKT (K_DIM / BK)             // 64

// ---------------- scratch ----------------------------------------------------
__device__ __align__(1024) __half g_Wh[(size_t)M_DIM * K_DIM];
__device__ __align__(1024) __half g_Xh[(size_t)BN_DIM * K_DIM];

// ---------------- helpers ----------------------------------------------------
__device__ __forceinline__ uint32_t smem_u32(const void* p) {
    uint32_t a;
    asm("{ .reg .u64 t; cvta.to.shared.u64 t, %1; cvt.u32.u64 %0, t; }" : "=r"(a) : "l"(p));
    return a;
}

#define CP16(dst_u32, src_ptr) \
    asm volatile("cp.async.cg.shared.global [%0], [%1], 16;" \
                 :: "r"(dst_u32), "l"(src_ptr) : "memory")
#define CP_COMMIT() asm volatile("cp.async.commit_group;" ::: "memory")
#define CP_WAIT(n)  asm volatile("cp.async.wait_group %0;" :: "n"(n) : "memory")

__device__ __forceinline__ void ldsm_x4(uint32_t* r, uint32_t addr) {
    asm volatile("ldmatrix.sync.aligned.m8n8.x4.shared.b16 {%0,%1,%2,%3}, [%4];"
        : "=r"(r[0]), "=r"(r[1]), "=r"(r[2]), "=r"(r[3]) : "r"(addr));
}

__device__ __forceinline__ void mma16816(float* d, const uint32_t* a, const uint32_t* b) {
    asm volatile(
        "mma.sync.aligned.m16n8k16.row.col.f32.f16.f16.f32 "
        "{%0,%1,%2,%3}, {%4,%5,%6,%7}, {%8,%9}, {%0,%1,%2,%3};"
        : "+f"(d[0]), "+f"(d[1]), "+f"(d[2]), "+f"(d[3])
        : "r"(a[0]), "r"(a[1]), "r"(a[2]), "r"(a[3]), "r"(b[0]), "r"(b[1]));
}

// ---------------- prep kernels -----------------------------------------------
// Fused zero + deterministic CSR scatter: build each dense fp16 W row in smem,
// write once coalesced.  Duplicate columns folded in fp32 (sorted runs).
__global__ void __launch_bounds__(128) buildw_kernel(
    const float* __restrict__ values, const int* __restrict__ row_offsets,
    const int* __restrict__ cols) {
    __shared__ __half row[K_DIM];                    // 8 KB
    const int m = blockIdx.x;

    uint4* r4 = reinterpret_cast<uint4*>(row);
    #pragma unroll
    for (int i = threadIdx.x; i < K_DIM / 8; i += 128)
        r4[i] = make_uint4(0u, 0u, 0u, 0u);
    __syncthreads();

    const int s = row_offsets[m], e = row_offsets[m + 1];
    for (int j = s + threadIdx.x; j < e; j += 128) {
        const int c = cols[j];
        if (j > s && cols[j - 1] == c) continue;     // not head of duplicate run
        float sum = values[j];
        int jj = j + 1;
        while (jj < e && cols[jj] == c) { sum += values[jj]; jj++; }
        row[c] = __float2half_rn(sum);
    }
    __syncthreads();

    uint4* dst = reinterpret_cast<uint4*>(g_Wh + (size_t)m * K_DIM);
    #pragma unroll
    for (int i = threadIdx.x; i < K_DIM / 8; i += 128)
        dst[i] = r4[i];
}

// fp32 -> fp16 conversion of a range of X, 8 elems/thread, single 16B store.
__global__ void __launch_bounds__(256) convx_kernel(const float* __restrict__ x,
                                                    size_t base) {
    const size_t i = base + ((size_t)blockIdx.x * 256 + threadIdx.x) * 8;
    const float4 a = *reinterpret_cast<const float4*>(&x[i]);
    const float4 b = *reinterpret_cast<const float4*>(&x[i + 4]);
    __half2 h[4];
    h[0] = __halves2half2(__float2half_rn(a.x), __float2half_rn(a.y));
    h[1] = __halves2half2(__float2half_rn(a.z), __float2half_rn(a.w));
    h[2] = __halves2half2(__float2half_rn(b.x), __float2half_rn(b.y));
    h[3] = __halves2half2(__float2half_rn(b.z), __float2half_rn(b.w));
    *reinterpret_cast<uint4*>(&g_Xh[i]) = *reinterpret_cast<const uint4*>(h);
}

// ---------------- GEMM -------------------------------------------------------
// C[M, bn_base:bn_base+32*BN] = Wh * Xh^T slice, fp32 accumulate.
// 128 threads, warp grid 2x2, warp tile 64x64.  2 CTAs/SM.
__global__ void __launch_bounds__(128, 2) gemm_kernel(float* __restrict__ out,
                                                      int bn_base) {
    extern __shared__ char smem[];
    const int tid  = threadIdx.x;
    const int wid  = tid >> 5;
    const int lane = tid & 31;
    const int grp  = lane >> 2;
    const int tig  = lane & 3;
    const int wm0  = (wid & 1) * 64;
    const int wn0  = (wid >> 1) * 64;
    const int m0   = blockIdx.x * BM;
    const int bn0  = bn_base + blockIdx.y * BN;

    const uint32_t sbase = smem_u32(smem);

    // ldmatrix lane-derived address components
    const int a_row_l = (lane & 7) + 8 * ((lane >> 3) & 1);
    const int a_kx    = 16 * ((lane >> 4) & 1);
    const int b_row_l = (lane & 7) + 8 * ((lane >> 4) & 1);
    const int b_kx    = 16 * ((lane >> 3) & 1);

    const __half* gA = g_Wh + (size_t)m0  * K_DIM;
    const __half* gB = g_Xh + (size_t)bn0 * K_DIM;

    // cp.async per stage: 1024 chunks A + 1024 chunks B (16 B each), 128 thr
    // -> 8 A + 8 B chunks per thread.  chunk c: row = c>>3, ch = c&7.
    #define LOAD_STAGE(stg, ktidx) do {                                         \
        const uint32_t sb_ = sbase + (stg) * STAGE_BYTES;                       \
        const int kh_ = (ktidx) * BK;                                           \
        _Pragma("unroll")                                                       \
        for (int i_ = 0; i_ < 8; i_++) {                                        \
            const int c_   = tid + i_ * 128;                                    \
            const int row_ = c_ >> 3, ch_ = c_ & 7;                             \
            const uint32_t d_ = sb_ + row_ * TRB + ch_ * 16;                    \
            const size_t  g_  = (size_t)row_ * K_DIM + kh_ + ch_ * 8;           \
            CP16(d_, gA + g_);                                                  \
            CP16(d_ + A_TILE_BYTES, gB + g_);                                   \
        }                                                                       \
    } while (0)

    #pragma unroll
    for (int s = 0; s < NSTAGE - 1; s++) { LOAD_STAGE(s, s); CP_COMMIT(); }

    float acc[4][8][4];
    #pragma unroll
    for (int mt = 0; mt < 4; mt++)
        #pragma unroll
        for (int nt = 0; nt < 8; nt++)
            #pragma unroll
            for (int r = 0; r < 4; r++) acc[mt][nt][r] = 0.f;

    for (int kt = 0; kt < NKT; kt++) {
        CP_WAIT(NSTAGE - 2);
        __syncthreads();
        if (kt + NSTAGE - 1 < NKT) LOAD_STAGE((kt + NSTAGE - 1) % NSTAGE, kt + NSTAGE - 1);
        CP_COMMIT();

        const uint32_t st = sbase + (kt % NSTAGE) * STAGE_BYTES;
        const uint32_t sA = st;
        const uint32_t sB = st + A_TILE_BYTES;

        #pragma unroll
        for (int ks = 0; ks < 4; ks++) {
            const int kb = ks * 32;
            uint32_t bf[8][2];
            #pragma unroll
            for (int ntp = 0; ntp < 4; ntp++) {
                uint32_t r[4];
                ldsm_x4(r, sB + (wn0 + 16 * ntp + b_row_l) * TRB + kb + b_kx);
                bf[2 * ntp][0]     = r[0];
                bf[2 * ntp][1]     = r[1];
                bf[2 * ntp + 1][0] = r[2];
                bf[2 * ntp + 1][1] = r[3];
            }
            uint32_t ah[4][4];
            #pragma unroll
            for (int mt = 0; mt < 4; mt++)
                ldsm_x4(ah[mt], sA + (wm0 + 16 * mt + a_row_l) * TRB + kb + a_kx);
            #pragma unroll
            for (int mt = 0; mt < 4; mt++)
                #pragma unroll
                for (int nt = 0; nt < 8; nt++)
                    mma16816(acc[mt][nt], ah[mt], bf[nt]);
        }
    }

    // epilogue
    const int b  = bn0 >> 11;               // / N_DIM
    const int nb = bn0 & (N_DIM - 1);
    float* ob = out + (size_t)b * M_DIM * N_DIM;
    #pragma unroll
    for (int mt = 0; mt < 4; mt++) {
        const int row = m0 + wm0 + 16 * mt + grp;
        #pragma unroll
        for (int nt = 0; nt < 8; nt++) {
            const int col = nb + wn0 + 8 * nt + 2 * tig;
            *reinterpret_cast<float2*>(ob + (size_t)row * N_DIM + col) =
                make_float2(acc[mt][nt][0], acc[mt][nt][1]);
            *reinterpret_cast<float2*>(ob + (size_t)(row + 8) * N_DIM + col) =
                make_float2(acc[mt][nt][2], acc[mt][nt][3]);
        }
    }
}

// ---------------- host side --------------------------------------------------
extern "C" void kernel_launch(void* const* d_in, const int* in_sizes, int n_in,
                              void* d_out, int out_size) {
    const float* x           = (const float*)d_in[0];  // [B, N, K] == [BN, K]
    const float* values      = (const float*)d_in[1];
    const int*   row_offsets = (const int*)  d_in[2];
    const int*   col_indices = (const int*)  d_in[3];
    float*       out         = (float*)d_out;
    (void)in_sizes; (void)n_in; (void)out_size;

    static bool inited = false;
    static cudaStream_t sW, sG;
    static cudaEvent_t evFork, evW, evX0, evG0;
    if (!inited) {
        cudaStreamCreateWithFlags(&sW, cudaStreamNonBlocking);
        cudaStreamCreateWithFlags(&sG, cudaStreamNonBlocking);
        cudaEventCreateWithFlags(&evFork, cudaEventDisableTiming);
        cudaEventCreateWithFlags(&evW,    cudaEventDisableTiming);
        cudaEventCreateWithFlags(&evX0,   cudaEventDisableTiming);
        cudaEventCreateWithFlags(&evG0,   cudaEventDisableTiming);
        cudaFuncSetAttribute(gemm_kernel,
                             cudaFuncAttributeMaxDynamicSharedMemorySize, SMEM_TOTAL);
        inited = true;
    }

    const size_t xN   = (size_t)BN_DIM * K_DIM;   // 33.5M halves
    const size_t half = xN / 2;
    const unsigned cblk = (unsigned)(half / 8 / 256);

    // fork sW from the (captured) main stream
    cudaEventRecord(evFork, 0);
    cudaStreamWaitEvent(sW, evFork, 0);

    // W build on sW, X conversion chunks on the main stream
    buildw_kernel<<<M_DIM, 128, 0, sW>>>(values, row_offsets, col_indices);
    cudaEventRecord(evW, sW);

    convx_kernel<<<cblk, 256>>>(x, 0);
    cudaEventRecord(evX0, 0);
    convx_kernel<<<cblk, 256>>>(x, half);

    // gemm half 0 on sG: needs W + X[0:half)
    cudaStreamWaitEvent(sG, evW, 0);
    cudaStreamWaitEvent(sG, evX0, 0);
    gemm_kernel<<<dim3(M_DIM / BM, BN_DIM / BN / 2), 128, SMEM_TOTAL, sG>>>(out, 0);
    cudaEventRecord(evG0, sG);

    // gemm half 1 on main stream: needs W + X[half:) (implicit on this stream)
    cudaStreamWaitEvent(0, evW, 0);
    gemm_kernel<<<dim3(M_DIM / BM, BN_DIM / BN / 2), 128, SMEM_TOTAL>>>(out, BN_DIM / 2);

    // join
    cudaStreamWaitEvent(0, evG0, 0);
}